// round 15
// baseline (speedup 1.0000x reference)
#include <cuda_runtime.h>
#include <stdint.h>
#include <math.h>

#define BATCH    256
#define NQ       1000
#define NC       81
#define NELEM    (NQ*NC)     /* 81000 */
#define KTOP     100
#define NT       512
#define NW       (NT/32)     /* 16 warps */
#define CANDBUF  1024
#define NBIN1    2048
#define NBIN2    256
#define FULLM    0xFFFFFFFFu

__device__ __forceinline__ float sigm_precise(float x) { return 1.0f / (1.0f + expf(-x)); }
__device__ __forceinline__ float sigm_fast(float x)    { return __fdividef(1.0f, 1.0f + __expf(-x)); }

__global__ void __launch_bounds__(NT, 2)
postproc_kernel(const float* __restrict__ logits,   // [B,Q,C]
                const float* __restrict__ obj,      // [B,Q]
                const float* __restrict__ boxesIn,  // [B,Q,4]
                const float* __restrict__ unk,      // [B,Q]
                const float* __restrict__ tsz,      // [B,2]
                float* __restrict__ out)
{
    const int b    = blockIdx.x;
    const int tid  = threadIdx.x;
    const int lane = tid & 31;
    const int w    = tid >> 5;

    __shared__ float          fac[NQ];      // exp(-obj)*(1-sig(unk))  (PRECISE)
    __shared__ float          lastv[NQ];    // exp(-obj)*sig(unk)      (PRECISE)
    __shared__ float          samp[NQ];     // probe samples (achieved values)
    __shared__ unsigned short qlist[NQ];
    __shared__ unsigned       hist[NBIN1];
    __shared__ int            s_t1;
    __shared__ unsigned       s_carry, s_T;
    __shared__ unsigned       s_cnt, s_nq;
    __shared__ unsigned       cbits[CANDBUF];
    __shared__ unsigned       cidx[CANDBUF];

    if (tid == 0) { s_cnt = 0; s_nq = 0; }

    const float* L = logits + (size_t)b * NELEM;

    // ---- per-query factors (precise; coalesced obj/unk loads) ----
    for (int q = tid; q < NQ; q += NT) {
        float o  = obj[b * NQ + q];
        float uu = unk[b * NQ + q];
        float op = expf(-o);
        float su = sigm_precise(uu);
        fac[q]   = op * (1.0f - su);
        lastv[q] = op * su;
    }
    __syncthreads();

    // ---- warp-per-row probe: 32 channels, one coalesced load + REDUX.MAX ----
    // sample(q) = max(fac[q]*sigm_fast(max logit c0..31), lastv[q]) — achieved value
    {
        for (unsigned q = (unsigned)w; q < NQ; q += 2u * NW) {
            unsigned qB = q + NW;
            bool hasB = qB < NQ;
            float a  = L[q * 81u + (unsigned)lane];                 // 128B coalesced
            float bb = hasB ? L[qB * 81u + (unsigned)lane] : 0.0f;
            unsigned ka = __float_as_uint(a);
            ka = (ka & 0x80000000u) ? ~ka : (ka | 0x80000000u);     // monotone map
            unsigned kb = __float_as_uint(bb);
            kb = (kb & 0x80000000u) ? ~kb : (kb | 0x80000000u);
            ka = __reduce_max_sync(FULLM, ka);                      // single REDUX
            kb = __reduce_max_sync(FULLM, kb);
            if (lane == 0) {
                unsigned ua = (ka & 0x80000000u) ? (ka ^ 0x80000000u) : ~ka;
                float ma = __uint_as_float(ua);
                samp[q] = fmaxf(fac[q] * sigm_fast(ma), lastv[q]);
                if (hasB) {
                    unsigned ub = (kb & 0x80000000u) ? (kb ^ 0x80000000u) : ~kb;
                    float mb = __uint_as_float(ub);
                    samp[qB] = fmaxf(fac[qB] * sigm_fast(mb), lastv[qB]);
                }
            }
        }
    }
    __syncthreads();

    const unsigned sb0 = (tid < NQ)      ? __float_as_uint(samp[tid])      : 0u;
    const unsigned sb1 = (tid + NT < NQ) ? __float_as_uint(samp[tid + NT]) : 0u;

    // ============== histogram select #1: floor Tq from achieved probe samples ==============
    for (int i = tid; i < NBIN1; i += NT) hist[i] = 0;
    __syncthreads();
    if (sb0) atomicAdd(&hist[sb0 >> 20], 1u);
    if (sb1) atomicAdd(&hist[sb1 >> 20], 1u);
    __syncthreads();
    if (w == 0) {
        unsigned csum = 0;
        for (int k = 0; k < NBIN1 / 32; ++k) csum += hist[lane * (NBIN1 / 32) + k];
        unsigned s = csum;
        #pragma unroll
        for (int off = 1; off < 32; off <<= 1) {
            unsigned v = __shfl_down_sync(FULLM, s, off);
            if (lane + off < 32) s += v;
        }
        unsigned snext = __shfl_down_sync(FULLM, s, 1);
        if (lane == 31) snext = 0;
        if (lane == 0 && s < KTOP) s_t1 = -1;
        if (s >= KTOP && snext < KTOP) {
            unsigned acc = snext; int t = 0; unsigned carry = 0;
            for (int kk = NBIN1 / 32 - 1; kk >= 0; --kk) {
                unsigned h = hist[lane * (NBIN1 / 32) + kk];
                if (acc + h >= KTOP) { t = lane * (NBIN1 / 32) + kk; carry = acc; break; }
                acc += h;
            }
            s_t1 = t; s_carry = carry;
        }
    }
    __syncthreads();
    float Tq = 0.0f;
    {
        int t1 = s_t1;
        if (t1 >= 0) {
            if (tid < NBIN2) hist[tid] = 0;
            __syncthreads();
            if ((int)(sb0 >> 20) == t1) atomicAdd(&hist[(sb0 >> 12) & 255u], 1u);
            if ((int)(sb1 >> 20) == t1) atomicAdd(&hist[(sb1 >> 12) & 255u], 1u);
            __syncthreads();
            if (w == 0) {
                unsigned K2 = KTOP - s_carry;
                unsigned csum = 0;
                for (int k = 0; k < NBIN2 / 32; ++k) csum += hist[lane * (NBIN2 / 32) + k];
                unsigned s = csum;
                #pragma unroll
                for (int off = 1; off < 32; off <<= 1) {
                    unsigned v = __shfl_down_sync(FULLM, s, off);
                    if (lane + off < 32) s += v;
                }
                unsigned snext = __shfl_down_sync(FULLM, s, 1);
                if (lane == 31) snext = 0;
                if (s >= K2 && snext < K2) {
                    unsigned acc = snext; int t2 = 0;
                    for (int kk = NBIN2 / 32 - 1; kk >= 0; --kk) {
                        unsigned h = hist[lane * (NBIN2 / 32) + kk];
                        if (acc + h >= K2) { t2 = lane * (NBIN2 / 32) + kk; break; }
                        acc += h;
                    }
                    s_T = ((unsigned)t1 << 20) | ((unsigned)t2 << 12);
                }
            }
            __syncthreads();
            Tq = __uint_as_float(s_T) * 0.99997f;   // query-prune threshold (valid floor w/ margin)
        }
    }

    // ---- survivor-query compaction (ballot-aggregated; pruned queries never loaded) ----
    for (int qb = 0; qb < NQ; qb += NT) {
        int q = qb + tid;
        bool p = (q < NQ) && (fac[q] >= Tq);
        unsigned m = __ballot_sync(FULLM, p);
        unsigned base = 0;
        if (lane == 0 && m) base = atomicAdd(&s_nq, (unsigned)__popc(m));
        base = __shfl_sync(FULLM, base, 0);
        if (p) qlist[base + __popc(m & ((1u << lane) - 1u))] = (unsigned short)q;
    }
    __syncthreads();
    const unsigned nq = s_nq;

    // ---- scan survivors: half-warp per query, 2-wide software pipeline, per-lane top-4 ----
    unsigned b0 = 0, b1 = 0, b2 = 0, b3 = 0;
    unsigned i0 = 0xFFFFFFFFu, i1 = 0xFFFFFFFFu, i2 = 0xFFFFFFFFu, i3 = 0xFFFFFFFFu;
    const unsigned hw = (unsigned)tid >> 4, j = (unsigned)tid & 15u;
    const unsigned STEP = NT / 16;   /* 32 half-warps */

    #define TOP4_UPDATE(PB, EE)                                                        \
        if ((PB) > b3) {                                                               \
            if ((PB) > b1) {                                                           \
                if ((PB) > b0) { b3=b2;i3=i2; b2=b1;i2=i1; b1=b0;i1=i0; b0=(PB);i0=(EE); } \
                else           { b3=b2;i3=i2; b2=b1;i2=i1; b1=(PB);i1=(EE); }          \
            } else {                                                                   \
                if ((PB) > b2) { b3=b2;i3=i2; b2=(PB);i2=(EE); }                       \
                else           { b3=(PB);i3=(EE); }                                    \
            }                                                                          \
        }

    for (unsigned s = hw; s < nq; s += 2u * STEP) {
        unsigned qA = qlist[s];
        bool hasB = (s + STEP) < nq;
        unsigned qB = hasB ? qlist[s + STEP] : qA;
        const float* LA = L + qA * 81u;
        const float* LB = L + qB * 81u;
        float vA[4], vB[4];
        #pragma unroll
        for (int k = 0; k < 4; ++k) {   // 8 independent loads batched up front (c<=63 in-bounds)
            unsigned c = j + 16u * (unsigned)k;
            vA[k] = LA[c];
            vB[k] = LB[c];
        }
        float fA = fac[qA];
        #pragma unroll
        for (int k = 0; k < 4; ++k) {
            unsigned c = j + 16u * (unsigned)k;
            if (c < 60u) {
                float p = fA * sigm_fast(vA[k]);
                unsigned pb = __float_as_uint(p);
                unsigned ee = qA * 81u + c;
                TOP4_UPDATE(pb, ee)
            }
        }
        if (hasB) {
            float fB = fac[qB];
            #pragma unroll
            for (int k = 0; k < 4; ++k) {
                unsigned c = j + 16u * (unsigned)k;
                if (c < 60u) {
                    float p = fB * sigm_fast(vB[k]);
                    unsigned pb = __float_as_uint(p);
                    unsigned ee = qB * 81u + c;
                    TOP4_UPDATE(pb, ee)
                }
            }
        }
    }
    #undef TOP4_UPDATE

    const unsigned lb0 = (tid < NQ)      ? __float_as_uint(lastv[tid])      : 0u;
    const unsigned lb1 = (tid + NT < NQ) ? __float_as_uint(lastv[tid + NT]) : 0u;
    __syncthreads();

    // ============== histogram select #2: tight T_keep over kept top-4s + lastv ==============
    for (int i = tid; i < NBIN1; i += NT) hist[i] = 0;
    __syncthreads();
    if (b0)  atomicAdd(&hist[b0  >> 20], 1u);
    if (b1)  atomicAdd(&hist[b1  >> 20], 1u);
    if (b2)  atomicAdd(&hist[b2  >> 20], 1u);
    if (b3)  atomicAdd(&hist[b3  >> 20], 1u);
    if (lb0) atomicAdd(&hist[lb0 >> 20], 1u);
    if (lb1) atomicAdd(&hist[lb1 >> 20], 1u);
    __syncthreads();
    if (w == 0) {
        unsigned csum = 0;
        for (int k = 0; k < NBIN1 / 32; ++k) csum += hist[lane * (NBIN1 / 32) + k];
        unsigned s = csum;
        #pragma unroll
        for (int off = 1; off < 32; off <<= 1) {
            unsigned v = __shfl_down_sync(FULLM, s, off);
            if (lane + off < 32) s += v;
        }
        unsigned snext = __shfl_down_sync(FULLM, s, 1);
        if (lane == 31) snext = 0;
        if (lane == 0 && s < KTOP) s_t1 = -1;
        if (s >= KTOP && snext < KTOP) {
            unsigned acc = snext; int t = 0; unsigned carry = 0;
            for (int kk = NBIN1 / 32 - 1; kk >= 0; --kk) {
                unsigned h = hist[lane * (NBIN1 / 32) + kk];
                if (acc + h >= KTOP) { t = lane * (NBIN1 / 32) + kk; carry = acc; break; }
                acc += h;
            }
            s_t1 = t; s_carry = carry;
        }
    }
    __syncthreads();
    unsigned T_keep = 0u;
    {
        int t1 = s_t1;
        if (t1 >= 0) {
            if (tid < NBIN2) hist[tid] = 0;
            __syncthreads();
            if ((int)(b0  >> 20) == t1) atomicAdd(&hist[(b0  >> 12) & 255u], 1u);
            if ((int)(b1  >> 20) == t1) atomicAdd(&hist[(b1  >> 12) & 255u], 1u);
            if ((int)(b2  >> 20) == t1) atomicAdd(&hist[(b2  >> 12) & 255u], 1u);
            if ((int)(b3  >> 20) == t1) atomicAdd(&hist[(b3  >> 12) & 255u], 1u);
            if ((int)(lb0 >> 20) == t1) atomicAdd(&hist[(lb0 >> 12) & 255u], 1u);
            if ((int)(lb1 >> 20) == t1) atomicAdd(&hist[(lb1 >> 12) & 255u], 1u);
            __syncthreads();
            if (w == 0) {
                unsigned K2 = KTOP - s_carry;
                unsigned csum = 0;
                for (int k = 0; k < NBIN2 / 32; ++k) csum += hist[lane * (NBIN2 / 32) + k];
                unsigned s = csum;
                #pragma unroll
                for (int off = 1; off < 32; off <<= 1) {
                    unsigned v = __shfl_down_sync(FULLM, s, off);
                    if (lane + off < 32) s += v;
                }
                unsigned snext = __shfl_down_sync(FULLM, s, 1);
                if (lane == 31) snext = 0;
                if (s >= K2 && snext < K2) {
                    unsigned acc = snext; int t2 = 0;
                    for (int kk = NBIN2 / 32 - 1; kk >= 0; --kk) {
                        unsigned h = hist[lane * (NBIN2 / 32) + kk];
                        if (acc + h >= K2) { t2 = lane * (NBIN2 / 32) + kk; break; }
                        acc += h;
                    }
                    s_T = ((unsigned)t1 << 20) | ((unsigned)t2 << 12);
                }
            }
            __syncthreads();
            unsigned Tb = s_T;
            if (Tb != 0u) T_keep = __float_as_uint(__uint_as_float(Tb) * 0.99998f);
        }
    }

    // ---- collect candidates (ballot-aggregated): provable superset of top-100 ----
    {
        bool pr; unsigned m, base, pos;
        #define PUSH(P, IDX)                                                          \
            pr = (P);                                                                 \
            m = __ballot_sync(FULLM, pr);                                             \
            base = 0;                                                                 \
            if (lane == 0 && m) base = atomicAdd(&s_cnt, (unsigned)__popc(m));        \
            base = __shfl_sync(FULLM, base, 0);                                       \
            if (pr) { pos = base + __popc(m & ((1u << lane) - 1u));                   \
                      if (pos < CANDBUF) cidx[pos] = (IDX); }
        PUSH(b0 >= T_keep && i0 != 0xFFFFFFFFu, i0)
        PUSH(b1 >= T_keep && i1 != 0xFFFFFFFFu, i1)
        PUSH(b2 >= T_keep && i2 != 0xFFFFFFFFu, i2)
        PUSH(b3 >= T_keep && i3 != 0xFFFFFFFFu, i3)
        PUSH(lb0 >= T_keep && tid < NQ,      (unsigned)tid * 81u + 80u)
        PUSH(lb1 >= T_keep && tid + NT < NQ, ((unsigned)tid + NT) * 81u + 80u)
        #undef PUSH
    }

    if (b3 >= T_keep) {
        // this lane may have dropped qualifiers: rescan ONLY its own queries (cache-hot)
        for (unsigned s = hw; s < nq; s += STEP) {
            unsigned q = qlist[s];
            float f = fac[q];
            const float* Lq = L + q * 81u;
            #pragma unroll
            for (int k = 0; k < 4; ++k) {
                unsigned c = j + 16u * (unsigned)k;
                if (c < 60u) {
                    float p = f * sigm_fast(Lq[c]);
                    unsigned pb = __float_as_uint(p);
                    unsigned ee = q * 81u + c;
                    if (pb >= T_keep && ee != i0 && ee != i1 && ee != i2 && ee != i3) {
                        unsigned pos = atomicAdd(&s_cnt, 1u);
                        if (pos < CANDBUF) cidx[pos] = ee;
                    }
                }
            }
        }
    }
    __syncthreads();
    const unsigned nF = (s_cnt < CANDBUF) ? s_cnt : CANDBUF;

    // ---- recompute candidates PRECISELY (bit-identical to verified formula) ----
    for (unsigned i = tid; i < nF; i += NT) {
        unsigned e = cidx[i];
        unsigned q = e / 81u;
        unsigned c = e - q * 81u;
        float p = (c < 60u) ? fac[q] * sigm_precise(L[e]) : lastv[q];
        cbits[i] = __float_as_uint(p);
    }
    __syncthreads();

    // ---- exact rank ordering (precise value desc, index asc) and output ----
    const float* Bx = boxesIn + (size_t)b * NQ * 4;
    const float ih = tsz[b * 2 + 0];
    const float iw = tsz[b * 2 + 1];

    for (unsigned i = tid; i < nF; i += NT) {
        unsigned bi = cbits[i], xi = cidx[i];
        unsigned r = 0;
        for (unsigned jj = 0; jj < nF; jj++) {
            unsigned bj = cbits[jj], xj = cidx[jj];
            r += (bj > bi) || (bj == bi && xj < xi);
        }
        if (r < KTOP) {
            unsigned q = xi / 81u;
            unsigned c = xi - q * 81u;
            out[(size_t)b * KTOP + r]                        = __uint_as_float(bi);
            out[(size_t)BATCH * KTOP + (size_t)b * KTOP + r] = (float)c;
            float cx = Bx[q * 4 + 0], cy = Bx[q * 4 + 1];
            float ww = Bx[q * 4 + 2], hh = Bx[q * 4 + 3];
            float* ob = out + (size_t)2 * BATCH * KTOP + ((size_t)b * KTOP + r) * 4;
            ob[0] = (cx - 0.5f * ww) * iw;
            ob[1] = (cy - 0.5f * hh) * ih;
            ob[2] = (cx + 0.5f * ww) * iw;
            ob[3] = (cy + 0.5f * hh) * ih;
        }
    }
}

extern "C" void kernel_launch(void* const* d_in, const int* in_sizes, int n_in,
                              void* d_out, int out_size)
{
    const float* logits  = (const float*)d_in[0];  // (256,1000,81)
    const float* obj     = (const float*)d_in[1];  // (256,1000)
    const float* boxesIn = (const float*)d_in[2];  // (256,1000,4)
    const float* unk     = (const float*)d_in[3];  // (256,1000)
    const float* tsz     = (const float*)d_in[4];  // (256,2)
    float* out = (float*)d_out;
    (void)in_sizes; (void)n_in; (void)out_size;

    postproc_kernel<<<BATCH, NT>>>(logits, obj, boxesIn, unk, tsz, out);
}

// round 16
// speedup vs baseline: 1.5806x; 1.5806x over previous
#include <cuda_runtime.h>
#include <stdint.h>
#include <math.h>

#define BATCH    256
#define NQ       1000
#define NC       81
#define NELEM    (NQ*NC)     /* 81000 */
#define KTOP     100
#define NT       512
#define NW       (NT/32)     /* 16 warps */
#define CANDBUF  1024
#define NBIN1    2048
#define NBIN2    256
#define FULLM    0xFFFFFFFFu

__device__ __forceinline__ float sigm_precise(float x) { return 1.0f / (1.0f + expf(-x)); }
__device__ __forceinline__ float sigm_fast(float x)    { return __fdividef(1.0f, 1.0f + __expf(-x)); }

__global__ void __launch_bounds__(NT, 2)
postproc_kernel(const float* __restrict__ logits,   // [B,Q,C]
                const float* __restrict__ obj,      // [B,Q]
                const float* __restrict__ boxesIn,  // [B,Q,4]
                const float* __restrict__ unk,      // [B,Q]
                const float* __restrict__ tsz,      // [B,2]
                float* __restrict__ out)
{
    const int b    = blockIdx.x;
    const int tid  = threadIdx.x;
    const int lane = tid & 31;
    const int w    = tid >> 5;

    __shared__ float          fac[NQ];      // exp(-obj)*(1-sig(unk))  (PRECISE)
    __shared__ float          lastv[NQ];    // exp(-obj)*sig(unk)      (PRECISE)
    __shared__ unsigned short qlist[NQ];
    __shared__ unsigned       hist[NBIN1];
    __shared__ int            s_t1;
    __shared__ unsigned       s_carry, s_T;
    __shared__ unsigned       s_cnt, s_nq;
    __shared__ unsigned       cbits[CANDBUF];
    __shared__ unsigned       cidx[CANDBUF];

    if (tid == 0) { s_cnt = 0; s_nq = 0; }

    const float* L = logits + (size_t)b * NELEM;

    // ---- per-query factors (precise; coalesced obj/unk loads). NO probe phase. ----
    for (int q = tid; q < NQ; q += NT) {
        float o  = obj[b * NQ + q];
        float uu = unk[b * NQ + q];
        float op = expf(-o);
        float su = sigm_precise(uu);
        fac[q]   = op * (1.0f - su);
        lastv[q] = op * su;
    }
    __syncthreads();

    const unsigned lb0 = (tid < NQ)      ? __float_as_uint(lastv[tid])      : 0u;
    const unsigned lb1 = (tid + NT < NQ) ? __float_as_uint(lastv[tid + NT]) : 0u;

    // ============== histogram select #1: floor Tq = binned 100th of lastv ==============
    // lastv are PRECISE achieved candidate values => Tq <= P100_precise, no margin needed.
    for (int i = tid; i < NBIN1; i += NT) hist[i] = 0;
    __syncthreads();
    if (lb0) atomicAdd(&hist[lb0 >> 20], 1u);
    if (lb1) atomicAdd(&hist[lb1 >> 20], 1u);
    __syncthreads();
    if (w == 0) {
        unsigned csum = 0;
        for (int k = 0; k < NBIN1 / 32; ++k) csum += hist[lane * (NBIN1 / 32) + k];
        unsigned s = csum;
        #pragma unroll
        for (int off = 1; off < 32; off <<= 1) {
            unsigned v = __shfl_down_sync(FULLM, s, off);
            if (lane + off < 32) s += v;
        }
        unsigned snext = __shfl_down_sync(FULLM, s, 1);
        if (lane == 31) snext = 0;
        if (lane == 0 && s < KTOP) s_t1 = -1;
        if (s >= KTOP && snext < KTOP) {
            unsigned acc = snext; int t = 0; unsigned carry = 0;
            for (int kk = NBIN1 / 32 - 1; kk >= 0; --kk) {
                unsigned h = hist[lane * (NBIN1 / 32) + kk];
                if (acc + h >= KTOP) { t = lane * (NBIN1 / 32) + kk; carry = acc; break; }
                acc += h;
            }
            s_t1 = t; s_carry = carry;
        }
    }
    __syncthreads();
    float Tq = 0.0f;
    {
        int t1 = s_t1;
        if (t1 >= 0) {
            if (tid < NBIN2) hist[tid] = 0;
            __syncthreads();
            if ((int)(lb0 >> 20) == t1) atomicAdd(&hist[(lb0 >> 12) & 255u], 1u);
            if ((int)(lb1 >> 20) == t1) atomicAdd(&hist[(lb1 >> 12) & 255u], 1u);
            __syncthreads();
            if (w == 0) {
                unsigned K2 = KTOP - s_carry;
                unsigned csum = 0;
                for (int k = 0; k < NBIN2 / 32; ++k) csum += hist[lane * (NBIN2 / 32) + k];
                unsigned s = csum;
                #pragma unroll
                for (int off = 1; off < 32; off <<= 1) {
                    unsigned v = __shfl_down_sync(FULLM, s, off);
                    if (lane + off < 32) s += v;
                }
                unsigned snext = __shfl_down_sync(FULLM, s, 1);
                if (lane == 31) snext = 0;
                if (s >= K2 && snext < K2) {
                    unsigned acc = snext; int t2 = 0;
                    for (int kk = NBIN2 / 32 - 1; kk >= 0; --kk) {
                        unsigned h = hist[lane * (NBIN2 / 32) + kk];
                        if (acc + h >= K2) { t2 = lane * (NBIN2 / 32) + kk; break; }
                        acc += h;
                    }
                    s_T = ((unsigned)t1 << 20) | ((unsigned)t2 << 12);
                }
            }
            __syncthreads();
            Tq = __uint_as_float(s_T);   // bin floor of 100th lastv: valid prune threshold
        }
    }

    // ---- survivor-query compaction (ballot-aggregated; pruned queries never loaded) ----
    for (int qb = 0; qb < NQ; qb += NT) {
        int q = qb + tid;
        bool p = (q < NQ) && (fac[q] >= Tq);
        unsigned m = __ballot_sync(FULLM, p);
        unsigned base = 0;
        if (lane == 0 && m) base = atomicAdd(&s_nq, (unsigned)__popc(m));
        base = __shfl_sync(FULLM, base, 0);
        if (p) qlist[base + __popc(m & ((1u << lane) - 1u))] = (unsigned short)q;
    }
    __syncthreads();
    const unsigned nq = s_nq;

    // ---- scan survivors: half-warp per query, 2-wide software pipeline, per-lane top-4 ----
    unsigned b0 = 0, b1 = 0, b2 = 0, b3 = 0;
    unsigned i0 = 0xFFFFFFFFu, i1 = 0xFFFFFFFFu, i2 = 0xFFFFFFFFu, i3 = 0xFFFFFFFFu;
    const unsigned hw = (unsigned)tid >> 4, j = (unsigned)tid & 15u;
    const unsigned STEP = NT / 16;   /* 32 half-warps */

    #define TOP4_UPDATE(PB, EE)                                                        \
        if ((PB) > b3) {                                                               \
            if ((PB) > b1) {                                                           \
                if ((PB) > b0) { b3=b2;i3=i2; b2=b1;i2=i1; b1=b0;i1=i0; b0=(PB);i0=(EE); } \
                else           { b3=b2;i3=i2; b2=b1;i2=i1; b1=(PB);i1=(EE); }          \
            } else {                                                                   \
                if ((PB) > b2) { b3=b2;i3=i2; b2=(PB);i2=(EE); }                       \
                else           { b3=(PB);i3=(EE); }                                    \
            }                                                                          \
        }

    for (unsigned s = hw; s < nq; s += 2u * STEP) {
        unsigned qA = qlist[s];
        bool hasB = (s + STEP) < nq;
        unsigned qB = hasB ? qlist[s + STEP] : qA;
        const float* LA = L + qA * 81u;
        const float* LB = L + qB * 81u;
        float vA[4], vB[4];
        #pragma unroll
        for (int k = 0; k < 4; ++k) {   // 8 independent loads batched up front (c<=63 in-bounds)
            unsigned c = j + 16u * (unsigned)k;
            vA[k] = LA[c];
            vB[k] = LB[c];
        }
        float fA = fac[qA];
        #pragma unroll
        for (int k = 0; k < 4; ++k) {
            unsigned c = j + 16u * (unsigned)k;
            if (c < 60u) {
                float p = fA * sigm_fast(vA[k]);
                unsigned pb = __float_as_uint(p);
                unsigned ee = qA * 81u + c;
                TOP4_UPDATE(pb, ee)
            }
        }
        if (hasB) {
            float fB = fac[qB];
            #pragma unroll
            for (int k = 0; k < 4; ++k) {
                unsigned c = j + 16u * (unsigned)k;
                if (c < 60u) {
                    float p = fB * sigm_fast(vB[k]);
                    unsigned pb = __float_as_uint(p);
                    unsigned ee = qB * 81u + c;
                    TOP4_UPDATE(pb, ee)
                }
            }
        }
    }
    #undef TOP4_UPDATE
    __syncthreads();

    // ============== histogram select #2: tight T_keep over kept top-4s + lastv ==============
    for (int i = tid; i < NBIN1; i += NT) hist[i] = 0;
    __syncthreads();
    if (b0)  atomicAdd(&hist[b0  >> 20], 1u);
    if (b1)  atomicAdd(&hist[b1  >> 20], 1u);
    if (b2)  atomicAdd(&hist[b2  >> 20], 1u);
    if (b3)  atomicAdd(&hist[b3  >> 20], 1u);
    if (lb0) atomicAdd(&hist[lb0 >> 20], 1u);
    if (lb1) atomicAdd(&hist[lb1 >> 20], 1u);
    __syncthreads();
    if (w == 0) {
        unsigned csum = 0;
        for (int k = 0; k < NBIN1 / 32; ++k) csum += hist[lane * (NBIN1 / 32) + k];
        unsigned s = csum;
        #pragma unroll
        for (int off = 1; off < 32; off <<= 1) {
            unsigned v = __shfl_down_sync(FULLM, s, off);
            if (lane + off < 32) s += v;
        }
        unsigned snext = __shfl_down_sync(FULLM, s, 1);
        if (lane == 31) snext = 0;
        if (lane == 0 && s < KTOP) s_t1 = -1;
        if (s >= KTOP && snext < KTOP) {
            unsigned acc = snext; int t = 0; unsigned carry = 0;
            for (int kk = NBIN1 / 32 - 1; kk >= 0; --kk) {
                unsigned h = hist[lane * (NBIN1 / 32) + kk];
                if (acc + h >= KTOP) { t = lane * (NBIN1 / 32) + kk; carry = acc; break; }
                acc += h;
            }
            s_t1 = t; s_carry = carry;
        }
    }
    __syncthreads();
    unsigned T_keep = 0u;
    {
        int t1 = s_t1;
        if (t1 >= 0) {
            if (tid < NBIN2) hist[tid] = 0;
            __syncthreads();
            if ((int)(b0  >> 20) == t1) atomicAdd(&hist[(b0  >> 12) & 255u], 1u);
            if ((int)(b1  >> 20) == t1) atomicAdd(&hist[(b1  >> 12) & 255u], 1u);
            if ((int)(b2  >> 20) == t1) atomicAdd(&hist[(b2  >> 12) & 255u], 1u);
            if ((int)(b3  >> 20) == t1) atomicAdd(&hist[(b3  >> 12) & 255u], 1u);
            if ((int)(lb0 >> 20) == t1) atomicAdd(&hist[(lb0 >> 12) & 255u], 1u);
            if ((int)(lb1 >> 20) == t1) atomicAdd(&hist[(lb1 >> 12) & 255u], 1u);
            __syncthreads();
            if (w == 0) {
                unsigned K2 = KTOP - s_carry;
                unsigned csum = 0;
                for (int k = 0; k < NBIN2 / 32; ++k) csum += hist[lane * (NBIN2 / 32) + k];
                unsigned s = csum;
                #pragma unroll
                for (int off = 1; off < 32; off <<= 1) {
                    unsigned v = __shfl_down_sync(FULLM, s, off);
                    if (lane + off < 32) s += v;
                }
                unsigned snext = __shfl_down_sync(FULLM, s, 1);
                if (lane == 31) snext = 0;
                if (s >= K2 && snext < K2) {
                    unsigned acc = snext; int t2 = 0;
                    for (int kk = NBIN2 / 32 - 1; kk >= 0; --kk) {
                        unsigned h = hist[lane * (NBIN2 / 32) + kk];
                        if (acc + h >= K2) { t2 = lane * (NBIN2 / 32) + kk; break; }
                        acc += h;
                    }
                    s_T = ((unsigned)t1 << 20) | ((unsigned)t2 << 12);
                }
            }
            __syncthreads();
            unsigned Tb = s_T;
            if (Tb != 0u) T_keep = __float_as_uint(__uint_as_float(Tb) * 0.99998f);
        }
    }

    // ---- collect candidates (ballot-aggregated): provable superset of top-100 ----
    {
        bool pr; unsigned m, base, pos;
        #define PUSH(P, IDX)                                                          \
            pr = (P);                                                                 \
            m = __ballot_sync(FULLM, pr);                                             \
            base = 0;                                                                 \
            if (lane == 0 && m) base = atomicAdd(&s_cnt, (unsigned)__popc(m));        \
            base = __shfl_sync(FULLM, base, 0);                                       \
            if (pr) { pos = base + __popc(m & ((1u << lane) - 1u));                   \
                      if (pos < CANDBUF) cidx[pos] = (IDX); }
        PUSH(b0 >= T_keep && i0 != 0xFFFFFFFFu, i0)
        PUSH(b1 >= T_keep && i1 != 0xFFFFFFFFu, i1)
        PUSH(b2 >= T_keep && i2 != 0xFFFFFFFFu, i2)
        PUSH(b3 >= T_keep && i3 != 0xFFFFFFFFu, i3)
        PUSH(lb0 >= T_keep && tid < NQ,      (unsigned)tid * 81u + 80u)
        PUSH(lb1 >= T_keep && tid + NT < NQ, ((unsigned)tid + NT) * 81u + 80u)
        #undef PUSH
    }

    if (b3 >= T_keep) {
        // this lane may have dropped qualifiers: rescan ONLY its own queries (cache-hot)
        for (unsigned s = hw; s < nq; s += STEP) {
            unsigned q = qlist[s];
            float f = fac[q];
            const float* Lq = L + q * 81u;
            #pragma unroll
            for (int k = 0; k < 4; ++k) {
                unsigned c = j + 16u * (unsigned)k;
                if (c < 60u) {
                    float p = f * sigm_fast(Lq[c]);
                    unsigned pb = __float_as_uint(p);
                    unsigned ee = q * 81u + c;
                    if (pb >= T_keep && ee != i0 && ee != i1 && ee != i2 && ee != i3) {
                        unsigned pos = atomicAdd(&s_cnt, 1u);
                        if (pos < CANDBUF) cidx[pos] = ee;
                    }
                }
            }
        }
    }
    __syncthreads();
    const unsigned nF = (s_cnt < CANDBUF) ? s_cnt : CANDBUF;

    // ---- recompute candidates PRECISELY (bit-identical to verified formula) ----
    for (unsigned i = tid; i < nF; i += NT) {
        unsigned e = cidx[i];
        unsigned q = e / 81u;
        unsigned c = e - q * 81u;
        float p = (c < 60u) ? fac[q] * sigm_precise(L[e]) : lastv[q];
        cbits[i] = __float_as_uint(p);
    }
    __syncthreads();

    // ---- exact rank ordering (precise value desc, index asc) and output ----
    const float* Bx = boxesIn + (size_t)b * NQ * 4;
    const float ih = tsz[b * 2 + 0];
    const float iw = tsz[b * 2 + 1];

    for (unsigned i = tid; i < nF; i += NT) {
        unsigned bi = cbits[i], xi = cidx[i];
        unsigned r = 0;
        for (unsigned jj = 0; jj < nF; jj++) {
            unsigned bj = cbits[jj], xj = cidx[jj];
            r += (bj > bi) || (bj == bi && xj < xi);
        }
        if (r < KTOP) {
            unsigned q = xi / 81u;
            unsigned c = xi - q * 81u;
            out[(size_t)b * KTOP + r]                        = __uint_as_float(bi);
            out[(size_t)BATCH * KTOP + (size_t)b * KTOP + r] = (float)c;
            float cx = Bx[q * 4 + 0], cy = Bx[q * 4 + 1];
            float ww = Bx[q * 4 + 2], hh = Bx[q * 4 + 3];
            float* ob = out + (size_t)2 * BATCH * KTOP + ((size_t)b * KTOP + r) * 4;
            ob[0] = (cx - 0.5f * ww) * iw;
            ob[1] = (cy - 0.5f * hh) * ih;
            ob[2] = (cx + 0.5f * ww) * iw;
            ob[3] = (cy + 0.5f * hh) * ih;
        }
    }
}

extern "C" void kernel_launch(void* const* d_in, const int* in_sizes, int n_in,
                              void* d_out, int out_size)
{
    const float* logits  = (const float*)d_in[0];  // (256,1000,81)
    const float* obj     = (const float*)d_in[1];  // (256,1000)
    const float* boxesIn = (const float*)d_in[2];  // (256,1000,4)
    const float* unk     = (const float*)d_in[3];  // (256,1000)
    const float* tsz     = (const float*)d_in[4];  // (256,2)
    float* out = (float*)d_out;
    (void)in_sizes; (void)n_in; (void)out_size;

    postproc_kernel<<<BATCH, NT>>>(logits, obj, boxesIn, unk, tsz, out);
}

// round 17
// speedup vs baseline: 1.6028x; 1.0141x over previous
#include <cuda_runtime.h>
#include <stdint.h>
#include <math.h>

#define BATCH    256
#define NQ       1000
#define NC       81
#define NELEM    (NQ*NC)     /* 81000 */
#define KTOP     100
#define NT       512
#define NW       (NT/32)     /* 16 warps */
#define CANDBUF  1024
#define NBIN1    2048
#define NBIN2    256
#define FULLM    0xFFFFFFFFu

__device__ __forceinline__ float sigm_precise(float x) { return 1.0f / (1.0f + expf(-x)); }
__device__ __forceinline__ float sigm_fast(float x)    { return __fdividef(1.0f, 1.0f + __expf(-x)); }

__global__ void __launch_bounds__(NT, 2)
postproc_kernel(const float* __restrict__ logits,   // [B,Q,C]
                const float* __restrict__ obj,      // [B,Q]
                const float* __restrict__ boxesIn,  // [B,Q,4]
                const float* __restrict__ unk,      // [B,Q]
                const float* __restrict__ tsz,      // [B,2]
                float* __restrict__ out)
{
    const int b    = blockIdx.x;
    const int tid  = threadIdx.x;
    const int lane = tid & 31;
    const int w    = tid >> 5;

    __shared__ float          fac[NQ];      // fast exp(-obj)*(1-sig(unk))
    __shared__ float          lastv[NQ];    // fast exp(-obj)*sig(unk)
    __shared__ unsigned short qlist[NQ];
    __shared__ unsigned       hist[NBIN1];
    __shared__ int            s_t1;
    __shared__ unsigned       s_carry, s_T;
    __shared__ unsigned       s_cnt, s_nq;
    __shared__ unsigned       cbits[CANDBUF];
    __shared__ unsigned       cidx[CANDBUF];

    if (tid == 0) { s_cnt = 0; s_nq = 0; }

    const float* L = logits + (size_t)b * NELEM;

    // ---- fused: hist zero + per-query factors (FAST intrinsics; precision restored
    //      per-candidate in the recompute phase). One barrier serves both. ----
    for (int i = tid; i < NBIN1; i += NT) hist[i] = 0;
    for (int q = tid; q < NQ; q += NT) {
        float o  = obj[b * NQ + q];
        float uu = unk[b * NQ + q];
        float op = __expf(-o);
        float su = sigm_fast(uu);
        fac[q]   = op * (1.0f - su);
        lastv[q] = op * su;
    }
    __syncthreads();

    const unsigned lb0 = (tid < NQ)      ? __float_as_uint(lastv[tid])      : 0u;
    const unsigned lb1 = (tid + NT < NQ) ? __float_as_uint(lastv[tid + NT]) : 0u;

    // ============== histogram select #1: floor Tq = binned 100th of lastv (fast) ==============
    if (lb0) atomicAdd(&hist[lb0 >> 20], 1u);
    if (lb1) atomicAdd(&hist[lb1 >> 20], 1u);
    __syncthreads();
    if (w == 0) {
        unsigned csum = 0;
        for (int k = 0; k < NBIN1 / 32; ++k) csum += hist[lane * (NBIN1 / 32) + k];
        unsigned s = csum;
        #pragma unroll
        for (int off = 1; off < 32; off <<= 1) {
            unsigned v = __shfl_down_sync(FULLM, s, off);
            if (lane + off < 32) s += v;
        }
        unsigned snext = __shfl_down_sync(FULLM, s, 1);
        if (lane == 31) snext = 0;
        if (lane == 0 && s < KTOP) s_t1 = -1;
        if (s >= KTOP && snext < KTOP) {
            unsigned acc = snext; int t = 0; unsigned carry = 0;
            for (int kk = NBIN1 / 32 - 1; kk >= 0; --kk) {
                unsigned h = hist[lane * (NBIN1 / 32) + kk];
                if (acc + h >= KTOP) { t = lane * (NBIN1 / 32) + kk; carry = acc; break; }
                acc += h;
            }
            s_t1 = t; s_carry = carry;
        }
    }
    __syncthreads();
    float Tq = 0.0f;
    {
        int t1 = s_t1;
        if (t1 >= 0) {
            if (tid < NBIN2) hist[tid] = 0;
            __syncthreads();
            if ((int)(lb0 >> 20) == t1) atomicAdd(&hist[(lb0 >> 12) & 255u], 1u);
            if ((int)(lb1 >> 20) == t1) atomicAdd(&hist[(lb1 >> 12) & 255u], 1u);
            __syncthreads();
            if (w == 0) {
                unsigned K2 = KTOP - s_carry;
                unsigned csum = 0;
                for (int k = 0; k < NBIN2 / 32; ++k) csum += hist[lane * (NBIN2 / 32) + k];
                unsigned s = csum;
                #pragma unroll
                for (int off = 1; off < 32; off <<= 1) {
                    unsigned v = __shfl_down_sync(FULLM, s, off);
                    if (lane + off < 32) s += v;
                }
                unsigned snext = __shfl_down_sync(FULLM, s, 1);
                if (lane == 31) snext = 0;
                if (s >= K2 && snext < K2) {
                    unsigned acc = snext; int t2 = 0;
                    for (int kk = NBIN2 / 32 - 1; kk >= 0; --kk) {
                        unsigned h = hist[lane * (NBIN2 / 32) + kk];
                        if (acc + h >= K2) { t2 = lane * (NBIN2 / 32) + kk; break; }
                        acc += h;
                    }
                    s_T = ((unsigned)t1 << 20) | ((unsigned)t2 << 12);
                }
            }
            __syncthreads();
            Tq = __uint_as_float(s_T) * 0.99997f;   // margin >> fast-math error: valid floor
        }
    }

    // ---- survivor-query compaction (ballot-aggregated; pruned queries never loaded) ----
    for (int qb = 0; qb < NQ; qb += NT) {
        int q = qb + tid;
        bool p = (q < NQ) && (fac[q] >= Tq);
        unsigned m = __ballot_sync(FULLM, p);
        unsigned base = 0;
        if (lane == 0 && m) base = atomicAdd(&s_nq, (unsigned)__popc(m));
        base = __shfl_sync(FULLM, base, 0);
        if (p) qlist[base + __popc(m & ((1u << lane) - 1u))] = (unsigned short)q;
    }
    __syncthreads();
    const unsigned nq = s_nq;

    // ---- scan survivors: half-warp per query, 2-wide software pipeline, per-lane top-4 ----
    unsigned b0 = 0, b1 = 0, b2 = 0, b3 = 0;
    unsigned i0 = 0xFFFFFFFFu, i1 = 0xFFFFFFFFu, i2 = 0xFFFFFFFFu, i3 = 0xFFFFFFFFu;
    const unsigned hw = (unsigned)tid >> 4, j = (unsigned)tid & 15u;
    const unsigned STEP = NT / 16;   /* 32 half-warps */

    #define TOP4_UPDATE(PB, EE)                                                        \
        if ((PB) > b3) {                                                               \
            if ((PB) > b1) {                                                           \
                if ((PB) > b0) { b3=b2;i3=i2; b2=b1;i2=i1; b1=b0;i1=i0; b0=(PB);i0=(EE); } \
                else           { b3=b2;i3=i2; b2=b1;i2=i1; b1=(PB);i1=(EE); }          \
            } else {                                                                   \
                if ((PB) > b2) { b3=b2;i3=i2; b2=(PB);i2=(EE); }                       \
                else           { b3=(PB);i3=(EE); }                                    \
            }                                                                          \
        }

    for (unsigned s = hw; s < nq; s += 2u * STEP) {
        unsigned qA = qlist[s];
        bool hasB = (s + STEP) < nq;
        unsigned qB = hasB ? qlist[s + STEP] : qA;
        const float* LA = L + qA * 81u;
        const float* LB = L + qB * 81u;
        float vA[4], vB[4];
        #pragma unroll
        for (int k = 0; k < 4; ++k) {   // 8 independent loads batched up front (c<=63 in-bounds)
            unsigned c = j + 16u * (unsigned)k;
            vA[k] = LA[c];
            vB[k] = LB[c];
        }
        float fA = fac[qA];
        #pragma unroll
        for (int k = 0; k < 4; ++k) {
            unsigned c = j + 16u * (unsigned)k;
            if (c < 60u) {
                float p = fA * sigm_fast(vA[k]);
                unsigned pb = __float_as_uint(p);
                unsigned ee = qA * 81u + c;
                TOP4_UPDATE(pb, ee)
            }
        }
        if (hasB) {
            float fB = fac[qB];
            #pragma unroll
            for (int k = 0; k < 4; ++k) {
                unsigned c = j + 16u * (unsigned)k;
                if (c < 60u) {
                    float p = fB * sigm_fast(vB[k]);
                    unsigned pb = __float_as_uint(p);
                    unsigned ee = qB * 81u + c;
                    TOP4_UPDATE(pb, ee)
                }
            }
        }
    }
    #undef TOP4_UPDATE
    __syncthreads();

    // ============== histogram select #2: tight T_keep over kept top-4s + lastv ==============
    for (int i = tid; i < NBIN1; i += NT) hist[i] = 0;
    __syncthreads();
    if (b0)  atomicAdd(&hist[b0  >> 20], 1u);
    if (b1)  atomicAdd(&hist[b1  >> 20], 1u);
    if (b2)  atomicAdd(&hist[b2  >> 20], 1u);
    if (b3)  atomicAdd(&hist[b3  >> 20], 1u);
    if (lb0) atomicAdd(&hist[lb0 >> 20], 1u);
    if (lb1) atomicAdd(&hist[lb1 >> 20], 1u);
    __syncthreads();
    if (w == 0) {
        unsigned csum = 0;
        for (int k = 0; k < NBIN1 / 32; ++k) csum += hist[lane * (NBIN1 / 32) + k];
        unsigned s = csum;
        #pragma unroll
        for (int off = 1; off < 32; off <<= 1) {
            unsigned v = __shfl_down_sync(FULLM, s, off);
            if (lane + off < 32) s += v;
        }
        unsigned snext = __shfl_down_sync(FULLM, s, 1);
        if (lane == 31) snext = 0;
        if (lane == 0 && s < KTOP) s_t1 = -1;
        if (s >= KTOP && snext < KTOP) {
            unsigned acc = snext; int t = 0; unsigned carry = 0;
            for (int kk = NBIN1 / 32 - 1; kk >= 0; --kk) {
                unsigned h = hist[lane * (NBIN1 / 32) + kk];
                if (acc + h >= KTOP) { t = lane * (NBIN1 / 32) + kk; carry = acc; break; }
                acc += h;
            }
            s_t1 = t; s_carry = carry;
        }
    }
    __syncthreads();
    unsigned T_keep = 0u;
    {
        int t1 = s_t1;
        if (t1 >= 0) {
            if (tid < NBIN2) hist[tid] = 0;
            __syncthreads();
            if ((int)(b0  >> 20) == t1) atomicAdd(&hist[(b0  >> 12) & 255u], 1u);
            if ((int)(b1  >> 20) == t1) atomicAdd(&hist[(b1  >> 12) & 255u], 1u);
            if ((int)(b2  >> 20) == t1) atomicAdd(&hist[(b2  >> 12) & 255u], 1u);
            if ((int)(b3  >> 20) == t1) atomicAdd(&hist[(b3  >> 12) & 255u], 1u);
            if ((int)(lb0 >> 20) == t1) atomicAdd(&hist[(lb0 >> 12) & 255u], 1u);
            if ((int)(lb1 >> 20) == t1) atomicAdd(&hist[(lb1 >> 12) & 255u], 1u);
            __syncthreads();
            if (w == 0) {
                unsigned K2 = KTOP - s_carry;
                unsigned csum = 0;
                for (int k = 0; k < NBIN2 / 32; ++k) csum += hist[lane * (NBIN2 / 32) + k];
                unsigned s = csum;
                #pragma unroll
                for (int off = 1; off < 32; off <<= 1) {
                    unsigned v = __shfl_down_sync(FULLM, s, off);
                    if (lane + off < 32) s += v;
                }
                unsigned snext = __shfl_down_sync(FULLM, s, 1);
                if (lane == 31) snext = 0;
                if (s >= K2 && snext < K2) {
                    unsigned acc = snext; int t2 = 0;
                    for (int kk = NBIN2 / 32 - 1; kk >= 0; --kk) {
                        unsigned h = hist[lane * (NBIN2 / 32) + kk];
                        if (acc + h >= K2) { t2 = lane * (NBIN2 / 32) + kk; break; }
                        acc += h;
                    }
                    s_T = ((unsigned)t1 << 20) | ((unsigned)t2 << 12);
                }
            }
            __syncthreads();
            unsigned Tb = s_T;
            if (Tb != 0u) T_keep = __float_as_uint(__uint_as_float(Tb) * 0.99998f);
        }
    }

    // ---- collect candidates (ballot-aggregated): provable superset of top-100 ----
    {
        bool pr; unsigned m, base, pos;
        #define PUSH(P, IDX)                                                          \
            pr = (P);                                                                 \
            m = __ballot_sync(FULLM, pr);                                             \
            base = 0;                                                                 \
            if (lane == 0 && m) base = atomicAdd(&s_cnt, (unsigned)__popc(m));        \
            base = __shfl_sync(FULLM, base, 0);                                       \
            if (pr) { pos = base + __popc(m & ((1u << lane) - 1u));                   \
                      if (pos < CANDBUF) cidx[pos] = (IDX); }
        PUSH(b0 >= T_keep && i0 != 0xFFFFFFFFu, i0)
        PUSH(b1 >= T_keep && i1 != 0xFFFFFFFFu, i1)
        PUSH(b2 >= T_keep && i2 != 0xFFFFFFFFu, i2)
        PUSH(b3 >= T_keep && i3 != 0xFFFFFFFFu, i3)
        PUSH(lb0 >= T_keep && tid < NQ,      (unsigned)tid * 81u + 80u)
        PUSH(lb1 >= T_keep && tid + NT < NQ, ((unsigned)tid + NT) * 81u + 80u)
        #undef PUSH
    }

    if (b3 >= T_keep) {
        // this lane may have dropped qualifiers: rescan ONLY its own queries (cache-hot)
        for (unsigned s = hw; s < nq; s += STEP) {
            unsigned q = qlist[s];
            float f = fac[q];
            const float* Lq = L + q * 81u;
            #pragma unroll
            for (int k = 0; k < 4; ++k) {
                unsigned c = j + 16u * (unsigned)k;
                if (c < 60u) {
                    float p = f * sigm_fast(Lq[c]);
                    unsigned pb = __float_as_uint(p);
                    unsigned ee = q * 81u + c;
                    if (pb >= T_keep && ee != i0 && ee != i1 && ee != i2 && ee != i3) {
                        unsigned pos = atomicAdd(&s_cnt, 1u);
                        if (pos < CANDBUF) cidx[pos] = ee;
                    }
                }
            }
        }
    }
    __syncthreads();
    const unsigned nF = (s_cnt < CANDBUF) ? s_cnt : CANDBUF;

    // ---- recompute candidates PRECISELY from raw inputs (bit-identical formula) ----
    for (unsigned i = tid; i < nF; i += NT) {
        unsigned e = cidx[i];
        unsigned q = e / 81u;
        unsigned c = e - q * 81u;
        float o  = obj[b * NQ + q];
        float uu = unk[b * NQ + q];
        float op = expf(-o);
        float su = sigm_precise(uu);
        float p;
        if (c < 60u) p = (op * (1.0f - su)) * sigm_precise(L[e]);
        else         p = op * su;
        cbits[i] = __float_as_uint(p);
    }
    __syncthreads();

    // ---- exact rank ordering (precise value desc, index asc) and output ----
    const float4* Bx4 = (const float4*)(boxesIn + (size_t)b * NQ * 4);
    const float ih = tsz[b * 2 + 0];
    const float iw = tsz[b * 2 + 1];

    for (unsigned i = tid; i < nF; i += NT) {
        unsigned bi = cbits[i], xi = cidx[i];
        unsigned r = 0;
        for (unsigned jj = 0; jj < nF; jj++) {
            unsigned bj = cbits[jj], xj = cidx[jj];
            r += (bj > bi) || (bj == bi && xj < xi);
        }
        if (r < KTOP) {
            unsigned q = xi / 81u;
            unsigned c = xi - q * 81u;
            out[(size_t)b * KTOP + r]                        = __uint_as_float(bi);
            out[(size_t)BATCH * KTOP + (size_t)b * KTOP + r] = (float)c;
            float4 bx = Bx4[q];
            float* ob = out + (size_t)2 * BATCH * KTOP + ((size_t)b * KTOP + r) * 4;
            ob[0] = (bx.x - 0.5f * bx.z) * iw;
            ob[1] = (bx.y - 0.5f * bx.w) * ih;
            ob[2] = (bx.x + 0.5f * bx.z) * iw;
            ob[3] = (bx.y + 0.5f * bx.w) * ih;
        }
    }
}

extern "C" void kernel_launch(void* const* d_in, const int* in_sizes, int n_in,
                              void* d_out, int out_size)
{
    const float* logits  = (const float*)d_in[0];  // (256,1000,81)
    const float* obj     = (const float*)d_in[1];  // (256,1000)
    const float* boxesIn = (const float*)d_in[2];  // (256,1000,4)
    const float* unk     = (const float*)d_in[3];  // (256,1000)
    const float* tsz     = (const float*)d_in[4];  // (256,2)
    float* out = (float*)d_out;
    (void)in_sizes; (void)n_in; (void)out_size;

    postproc_kernel<<<BATCH, NT>>>(logits, obj, boxesIn, unk, tsz, out);
}